// round 2
// baseline (speedup 1.0000x reference)
#include <cuda_runtime.h>
#include <cstdint>

// Shapes (fixed by the problem)
#define S_IN   2048
#define S_T    2048
#define BATCH  8
#define HID    64

#define TM     16          // t-rows per CTA
#define SC     128         // s-chunk size
#define NCHUNK (S_IN / SC) // 16
#define APITCH 68          // padded pitch for sA / sWT

// SMEM layout (floats):
//   sS  [TM][2048]      scores   32768
//   sBT [64][SC]        input^T   8192
//   sA  [TM][APITCH]    lin out   1088
#define SMEM_FLOATS (TM * S_IN + HID * SC + TM * APITCH)

__device__ __forceinline__ float warp_sum(float v) {
    v += __shfl_xor_sync(0xffffffffu, v, 16);
    v += __shfl_xor_sync(0xffffffffu, v, 8);
    v += __shfl_xor_sync(0xffffffffu, v, 4);
    v += __shfl_xor_sync(0xffffffffu, v, 2);
    v += __shfl_xor_sync(0xffffffffu, v, 1);
    return v;
}
__device__ __forceinline__ float warp_max(float v) {
    v = fmaxf(v, __shfl_xor_sync(0xffffffffu, v, 16));
    v = fmaxf(v, __shfl_xor_sync(0xffffffffu, v, 8));
    v = fmaxf(v, __shfl_xor_sync(0xffffffffu, v, 4));
    v = fmaxf(v, __shfl_xor_sync(0xffffffffu, v, 2));
    v = fmaxf(v, __shfl_xor_sync(0xffffffffu, v, 1));
    return v;
}

__global__ void __launch_bounds__(256, 1)
attn_fused_kernel(const float* __restrict__ inp,      // (S_IN, B, H)
                  const float* __restrict__ tgt,      // (S_T, B, H)
                  const unsigned char* __restrict__ msk, // (B, S_T, S_IN) bool
                  const float* __restrict__ Wm,       // (H, H)  W[o][h]
                  const float* __restrict__ bias,     // (H)
                  float* __restrict__ out)            // (B, S_T, S_IN)
{
    extern __shared__ float sm[];
    float* sS  = sm;                       // TM * 2048
    float* sBT = sm + TM * S_IN;           // 64 * SC  (transposed input chunk)
    float* sA  = sBT + HID * SC;           // TM * APITCH

    const int tid = threadIdx.x;
    const int b   = blockIdx.x >> 7;        // 8 batches
    const int t0  = (blockIdx.x & 127) << 4; // tile of 16 t-rows

    // ---------------- prefetch chunk 0 into registers ----------------
    const int lrow = tid & 127;   // s index within chunk
    const int half = tid >> 7;    // which 32-float half of the 64-float row
    float4 pf[8];
    {
        const float4* src = reinterpret_cast<const float4*>(
            inp + ((size_t)(lrow * BATCH + b)) * HID + half * 32);
        #pragma unroll
        for (int i = 0; i < 8; ++i) pf[i] = src[i];
    }

    // ---------------- stage W (transposed) + target tile in sS region ----------------
    float* sWT = sS;                 // 64 * APITCH floats
    float* sTg = sS + HID * APITCH;  // TM * 64 floats
    {
        const int o  = tid >> 2;
        const int hq = (tid & 3) * 16;
        #pragma unroll
        for (int k = 0; k < 4; ++k) {
            float4 wv = *reinterpret_cast<const float4*>(Wm + o * HID + hq + 4 * k);
            sWT[(hq + 4 * k + 0) * APITCH + o] = wv.x;
            sWT[(hq + 4 * k + 1) * APITCH + o] = wv.y;
            sWT[(hq + 4 * k + 2) * APITCH + o] = wv.z;
            sWT[(hq + 4 * k + 3) * APITCH + o] = wv.w;
        }
        const int r  = tid >> 4;
        const int hh = (tid & 15) * 4;
        *reinterpret_cast<float4*>(sTg + r * HID + hh) =
            *reinterpret_cast<const float4*>(tgt + ((size_t)((t0 + r) * BATCH + b)) * HID + hh);
    }
    __syncthreads();

    // ---------------- sA = target_tile @ W^T + bias ----------------
    {
        const int r  = tid >> 4;
        const int o0 = (tid & 15) * 4;
        float4 acc = *reinterpret_cast<const float4*>(bias + o0);
        #pragma unroll
        for (int h = 0; h < HID; ++h) {
            const float  tv = sTg[r * HID + h];
            const float4 wv = *reinterpret_cast<const float4*>(sWT + h * APITCH + o0);
            acc.x += tv * wv.x;
            acc.y += tv * wv.y;
            acc.z += tv * wv.z;
            acc.w += tv * wv.w;
        }
        *reinterpret_cast<float4*>(sA + r * APITCH + o0) = acc;
    }
    // (first loop __syncthreads() makes sA visible before it is read)

    const int wid  = tid >> 5;
    const int lane = tid & 31;
    const int r0   = (wid >> 1) * 4;            // 4-row group, warp-uniform
    const int g    = (wid & 1) * 32 + lane;     // s-pair index 0..63

    // ---------------- main loop over s-chunks ----------------
    for (int c = 0; c < NCHUNK; ++c) {
        __syncthreads();   // prev compute done reading sBT; sA visible (c==0)
        // transpose-store prefetched chunk into sBT[h][s]
        #pragma unroll
        for (int i = 0; i < 8; ++i) {
            const int h = half * 32 + i * 4;
            sBT[(h + 0) * SC + lrow] = pf[i].x;
            sBT[(h + 1) * SC + lrow] = pf[i].y;
            sBT[(h + 2) * SC + lrow] = pf[i].z;
            sBT[(h + 3) * SC + lrow] = pf[i].w;
        }
        __syncthreads();
        // prefetch next chunk (latency hidden by compute below)
        if (c + 1 < NCHUNK) {
            const float4* src = reinterpret_cast<const float4*>(
                inp + ((size_t)(((c + 1) * SC + lrow) * BATCH + b)) * HID + half * 32);
            #pragma unroll
            for (int i = 0; i < 8; ++i) pf[i] = src[i];
        }
        // 4x2 micro-tile: A loads are warp-uniform broadcasts, B is float2
        float2 a0 = {0.f, 0.f}, a1 = {0.f, 0.f}, a2 = {0.f, 0.f}, a3 = {0.f, 0.f};
        const float* bp = sBT + 2 * g;
        #pragma unroll
        for (int h = 0; h < HID; ++h) {
            const float2 bv = *reinterpret_cast<const float2*>(bp + h * SC);
            const float x0 = sA[(r0 + 0) * APITCH + h];
            const float x1 = sA[(r0 + 1) * APITCH + h];
            const float x2 = sA[(r0 + 2) * APITCH + h];
            const float x3 = sA[(r0 + 3) * APITCH + h];
            a0.x += x0 * bv.x;  a0.y += x0 * bv.y;
            a1.x += x1 * bv.x;  a1.y += x1 * bv.y;
            a2.x += x2 * bv.x;  a2.y += x2 * bv.y;
            a3.x += x3 * bv.x;  a3.y += x3 * bv.y;
        }
        float* dst = sS + c * SC + 2 * g;
        *reinterpret_cast<float2*>(dst + (r0 + 0) * S_IN) = a0;
        *reinterpret_cast<float2*>(dst + (r0 + 1) * S_IN) = a1;
        *reinterpret_cast<float2*>(dst + (r0 + 2) * S_IN) = a2;
        *reinterpret_cast<float2*>(dst + (r0 + 3) * S_IN) = a3;
    }
    __syncthreads();

    // ---------------- fused epilogue: mean -> abs/mask -> max -> exp -> normalize ----------------
    const float NEG_INF = __int_as_float(0xff800000);
    #pragma unroll
    for (int rr = 0; rr < 2; ++rr) {
        const int r = wid * 2 + rr;                  // warp handles rows 2w, 2w+1
        float* row = sS + r * S_IN;
        const size_t gbase = ((size_t)(b * S_T + (t0 + r))) * S_IN;

        // mean over s
        float s = 0.f;
        #pragma unroll
        for (int i = 0; i < 16; ++i) {
            const float4 v = *reinterpret_cast<const float4*>(row + i * 128 + lane * 4);
            s += (v.x + v.y) + (v.z + v.w);
        }
        s = warp_sum(s);
        const float mean = s * (1.0f / 2048.0f);

        // y = |x - mean|, apply mask (-inf), track max
        float m = NEG_INF;
        #pragma unroll
        for (int i = 0; i < 16; ++i) {
            float4 v = *reinterpret_cast<const float4*>(row + i * 128 + lane * 4);
            v.x = fabsf(v.x - mean);
            v.y = fabsf(v.y - mean);
            v.z = fabsf(v.z - mean);
            v.w = fabsf(v.w - mean);
            const unsigned int mk = *reinterpret_cast<const unsigned int*>(
                msk + gbase + i * 128 + lane * 4);
            if (mk & 0x000000FFu) v.x = NEG_INF;
            if (mk & 0x0000FF00u) v.y = NEG_INF;
            if (mk & 0x00FF0000u) v.z = NEG_INF;
            if (mk & 0xFF000000u) v.w = NEG_INF;
            *reinterpret_cast<float4*>(row + i * 128 + lane * 4) = v;
            m = fmaxf(m, fmaxf(fmaxf(v.x, v.y), fmaxf(v.z, v.w)));
        }
        m = warp_max(m);

        // e = exp(y - max); sum
        float l = 0.f;
        #pragma unroll
        for (int i = 0; i < 16; ++i) {
            float4 v = *reinterpret_cast<const float4*>(row + i * 128 + lane * 4);
            v.x = __expf(v.x - m);
            v.y = __expf(v.y - m);
            v.z = __expf(v.z - m);
            v.w = __expf(v.w - m);
            *reinterpret_cast<float4*>(row + i * 128 + lane * 4) = v;
            l += (v.x + v.y) + (v.z + v.w);
        }
        l = warp_sum(l);
        const float inv = 1.0f / l;

        // write normalized probabilities
        #pragma unroll
        for (int i = 0; i < 16; ++i) {
            float4 v = *reinterpret_cast<const float4*>(row + i * 128 + lane * 4);
            v.x *= inv; v.y *= inv; v.z *= inv; v.w *= inv;
            *reinterpret_cast<float4*>(out + gbase + i * 128 + lane * 4) = v;
        }
    }
}

extern "C" void kernel_launch(void* const* d_in, const int* in_sizes, int n_in,
                              void* d_out, int out_size)
{
    const float*         inp  = (const float*)d_in[0];
    const float*         tgt  = (const float*)d_in[1];
    const unsigned char* msk  = (const unsigned char*)d_in[2];
    const float*         Wm   = (const float*)d_in[3];
    const float*         bias = (const float*)d_in[4];
    float*               out  = (float*)d_out;

    const int smem_bytes = SMEM_FLOATS * (int)sizeof(float); // 168192 B
    cudaFuncSetAttribute(attn_fused_kernel,
                         cudaFuncAttributeMaxDynamicSharedMemorySize, smem_bytes);

    dim3 grid(BATCH * (S_T / TM));  // 1024 CTAs
    dim3 block(256);
    attn_fused_kernel<<<grid, block, smem_bytes>>>(inp, tgt, msk, Wm, bias, out);
}